// round 4
// baseline (speedup 1.0000x reference)
#include <cuda_runtime.h>
#include <cstdint>

// ============================================================================
// y[128, 11008] = x[128,4096] @ W[11008,4096]^T * scale + bias
// w_q arrives as int32 (harness widens int8 -> int32). Packed to s8 in-flight.
// Dual-level int8 quantization of x:  x ~ s_m*(q1 + q2/254)
// GEMM via mma.sync.m16n8k32.s8 (exact int32 accumulation), fp32 epilogue.
// ============================================================================

#define M_ROWS 128
#define K_DIM  4096
#define N_DIM  11008
#define N_TILE 128
#define N_BLOCKS (N_DIM / N_TILE)          // 86
#define K_STAGE 128                        // k elements per stage
#define NSTAGES 4
#define NUM_STEPS (K_DIM / K_STAGE)        // 32

#define SMEM_ROW 144                       // 128 + 16 pad (conflict-free LDS)
#define A_TILE_BYTES (M_ROWS * SMEM_ROW)   // 18432
#define B_TILE_BYTES (N_TILE * SMEM_ROW)   // 18432
#define STAGE_BYTES  (2 * A_TILE_BYTES + B_TILE_BYTES)   // 55296
#define SMEM_TOTAL   (NSTAGES * STAGE_BYTES)             // 221184 (< 227KB)

#define B_OFF  (2 * A_TILE_BYTES)

// ---- scratch (no cudaMalloc allowed) ----
__device__ __align__(1024) int8_t g_q1[M_ROWS * K_DIM];
__device__ __align__(1024) int8_t g_q2[M_ROWS * K_DIM];
__device__ float g_xscale[M_ROWS];

// ============================================================================
// helpers
// ============================================================================
__device__ __forceinline__ uint32_t smem_u32(const void* p) {
    uint32_t a;
    asm("{ .reg .u64 t; cvta.to.shared.u64 t, %1; cvt.u32.u64 %0, t; }"
        : "=r"(a) : "l"(p));
    return a;
}
__device__ __forceinline__ void cp16(uint32_t dst, const void* src) {
    asm volatile("cp.async.cg.shared.global [%0], [%1], 16;"
                 :: "r"(dst), "l"(src) : "memory");
}
__device__ __forceinline__ void cp_commit() {
    asm volatile("cp.async.commit_group;" ::: "memory");
}
template <int N>
__device__ __forceinline__ void cp_wait() {
    asm volatile("cp.async.wait_group %0;" :: "n"(N) : "memory");
}
__device__ __forceinline__ void mma_s8(int* d, const uint32_t* a, const uint32_t* b) {
    asm volatile(
        "mma.sync.aligned.m16n8k32.row.col.s32.s8.s8.s32 "
        "{%0,%1,%2,%3}, {%4,%5,%6,%7}, {%8,%9}, {%0,%1,%2,%3};"
        : "+r"(d[0]), "+r"(d[1]), "+r"(d[2]), "+r"(d[3])
        : "r"(a[0]), "r"(a[1]), "r"(a[2]), "r"(a[3]), "r"(b[0]), "r"(b[1]));
}
// 4 sign-extended int8-in-int32 -> one packed b32 (little-endian: byte i = v_i)
__device__ __forceinline__ uint32_t pack4(int4 v) {
    uint32_t lo = __byte_perm((uint32_t)v.x, (uint32_t)v.y, 0x0040);
    uint32_t hi = __byte_perm((uint32_t)v.z, (uint32_t)v.w, 0x0040);
    return __byte_perm(lo, hi, 0x5410);
}

// ============================================================================
// Kernel 1: quantize x rows -> (q1, q2) int8 + per-row scale
// ============================================================================
__global__ __launch_bounds__(128) void quant_x_kernel(const float* __restrict__ x) {
    int m = blockIdx.x;
    int tid = threadIdx.x;
    const float4* xr = reinterpret_cast<const float4*>(x + (size_t)m * K_DIM);

    float4 v[8];
    float vmax = 0.f;
#pragma unroll
    for (int i = 0; i < 8; i++) {
        v[i] = xr[tid + i * 128];
        vmax = fmaxf(vmax, fmaxf(fmaxf(fabsf(v[i].x), fabsf(v[i].y)),
                                 fmaxf(fabsf(v[i].z), fabsf(v[i].w))));
    }
#pragma unroll
    for (int o = 16; o > 0; o >>= 1)
        vmax = fmaxf(vmax, __shfl_xor_sync(0xffffffffu, vmax, o));

    __shared__ float smax[4];
    if ((tid & 31) == 0) smax[tid >> 5] = vmax;
    __syncthreads();
    vmax = fmaxf(fmaxf(smax[0], smax[1]), fmaxf(smax[2], smax[3]));

    float inv = (vmax > 0.f) ? (127.0f / vmax) : 0.0f;
    float sm  = (vmax > 0.f) ? (vmax / 127.0f) : 1.0f;
    if (tid == 0) g_xscale[m] = sm;

    char4* o1 = reinterpret_cast<char4*>(g_q1 + (size_t)m * K_DIM);
    char4* o2 = reinterpret_cast<char4*>(g_q2 + (size_t)m * K_DIM);

#pragma unroll
    for (int i = 0; i < 8; i++) {
        float t[4] = {v[i].x * inv, v[i].y * inv, v[i].z * inv, v[i].w * inv};
        char q1c[4], q2c[4];
#pragma unroll
        for (int j = 0; j < 4; j++) {
            float q1 = rintf(t[j]);
            float q2 = rintf((t[j] - q1) * 254.0f);
            q1c[j] = (char)(int)q1;
            q2c[j] = (char)(int)q2;
        }
        o1[tid + i * 128] = make_char4(q1c[0], q1c[1], q1c[2], q1c[3]);
        o2[tid + i * 128] = make_char4(q2c[0], q2c[1], q2c[2], q2c[3]);
    }
}

// ============================================================================
// Kernel 2: GEMM. 86 CTAs x 512 threads. CTA tile 128(M) x 128(N).
// 4x4 warp grid, warp tile 32x32. 4-stage ring:
//   A1/A2 (int8 from g_q1/g_q2): cp.async, 2 stages ahead
//   B (int32 W): LDG.128 2 stages ahead -> pack to s8 -> STS after compute
// Fragment loads: plain LDS.b32 at PTX-spec per-lane coordinates.
// ============================================================================
__global__ __launch_bounds__(512, 1) void gemm_i8_kernel(
    const int* __restrict__ w32,
    const float* __restrict__ scale,
    const float* __restrict__ bias,
    float* __restrict__ out)
{
    extern __shared__ char smem[];
    const uint32_t sb = smem_u32(smem);
    const int tid = threadIdx.x;
    const int wid = tid >> 5;
    const int lane = tid & 31;
    const int wm = wid & 3;        // warp M index (0..3)
    const int wn = wid >> 2;       // warp N index (0..3)
    const int n_base = blockIdx.x * N_TILE;

    // ---- A-side cp.async assignments (4 x 16B per stage per thread) --------
    uint32_t cpA_dst[4];
    const int8_t* cpA_src[4];
#pragma unroll
    for (int i = 0; i < 4; i++) {
        int c = tid + i * 512;           // [0, 2048)
        int which = c >> 10;             // 0:A1 1:A2
        int r = (c & 1023) >> 3;         // m row 0..127
        int col = (c & 7) * 16;          // k byte 0..112
        cpA_dst[i] = sb + which * A_TILE_BYTES + r * SMEM_ROW + col;
        cpA_src[i] = (which ? g_q2 : g_q1) + (size_t)r * K_DIM + col;
    }
    auto issueA = [&](int s) {
        uint32_t buf_off = (uint32_t)((s & (NSTAGES - 1)) * STAGE_BYTES);
        int k0 = s * K_STAGE;
#pragma unroll
        for (int i = 0; i < 4; i++)
            cp16(cpA_dst[i] + buf_off, cpA_src[i] + k0);
        cp_commit();
    };

    // ---- B-side: 8 x LDG.128 (int32x4) per thread per stage ----------------
    const int wr = tid >> 5;            // base n-row 0..15  (rows wr + 16j)
    const int c4 = (tid & 31) * 4;      // k (int32 index, also packed byte col)
    const int* wbase = w32 + (size_t)(n_base + wr) * K_DIM + c4;

    int4 breg[8];
    auto ldgB = [&](int s) {
        const int* p = wbase + s * K_STAGE;
#pragma unroll
        for (int j = 0; j < 8; j++)
            breg[j] = *reinterpret_cast<const int4*>(p + (size_t)j * 16 * K_DIM);
    };
    auto stsB = [&](int s) {
        char* dst = smem + (s & (NSTAGES - 1)) * STAGE_BYTES + B_OFF
                         + wr * SMEM_ROW + c4;
#pragma unroll
        for (int j = 0; j < 8; j++)
            *reinterpret_cast<uint32_t*>(dst + j * 16 * SMEM_ROW) = pack4(breg[j]);
    };

    // ---- prologue: stages 0,1 ----------------------------------------------
    issueA(0);
    issueA(1);
    ldgB(0); stsB(0);
    ldgB(1); stsB(1);

    // ---- per-lane fragment base pointers (PTX m16n8k32.s8 spec) ------------
    const int g  = lane >> 2;
    const int t4 = (lane & 3) * 4;
    const char* A1p = smem + (wm * 32 + g) * SMEM_ROW + t4;
    const char* Bp  = smem + B_OFF + (wn * 32 + g) * SMEM_ROW + t4;

    int acc1[2][4][4] = {};
    int acc2[2][4][4] = {};

    // ---- main loop ---------------------------------------------------------
    for (int s = 0; s < NUM_STEPS; s++) {
        cp_wait<1>();          // A stage s landed (this thread)
        __syncthreads();       // publish everyone's A + B(stage s)

        if (s + 2 < NUM_STEPS) { ldgB(s + 2); issueA(s + 2); }
        else                   { cp_commit(); }   // keep wait accounting sound

        const int buf = (s & (NSTAGES - 1)) * STAGE_BYTES;
#pragma unroll
        for (int ks = 0; ks < 4; ks++) {
            const int off = buf + ks * 32;
            uint32_t a1f[2][4], a2f[2][4], bfr[4][2];
#pragma unroll
            for (int mf = 0; mf < 2; mf++) {
                const char* r1 = A1p + off + mf * (16 * SMEM_ROW);
                a1f[mf][0] = *(const uint32_t*)(r1);
                a1f[mf][1] = *(const uint32_t*)(r1 + 8 * SMEM_ROW);
                a1f[mf][2] = *(const uint32_t*)(r1 + 16);
                a1f[mf][3] = *(const uint32_t*)(r1 + 8 * SMEM_ROW + 16);
                const char* r2 = r1 + A_TILE_BYTES;
                a2f[mf][0] = *(const uint32_t*)(r2);
                a2f[mf][1] = *(const uint32_t*)(r2 + 8 * SMEM_ROW);
                a2f[mf][2] = *(const uint32_t*)(r2 + 16);
                a2f[mf][3] = *(const uint32_t*)(r2 + 8 * SMEM_ROW + 16);
            }
#pragma unroll
            for (int nf = 0; nf < 4; nf++) {
                const char* rb = Bp + off + nf * (8 * SMEM_ROW);
                bfr[nf][0] = *(const uint32_t*)(rb);
                bfr[nf][1] = *(const uint32_t*)(rb + 16);
            }
#pragma unroll
            for (int mf = 0; mf < 2; mf++) {
#pragma unroll
                for (int nf = 0; nf < 4; nf++) {
                    mma_s8(acc1[mf][nf], a1f[mf], bfr[nf]);
                    mma_s8(acc2[mf][nf], a2f[mf], bfr[nf]);
                }
            }
        }

        if (s + 2 < NUM_STEPS) stsB(s + 2);   // ring distance 2 (!= s mod 4)
    }

    // ---- epilogue ----------------------------------------------------------
    const float sw = __ldg(scale);
    const int mrow0 = wm * 32 + g;
#pragma unroll
    for (int mf = 0; mf < 2; mf++) {
        int m0 = mrow0 + mf * 16;
        float f1a = sw * g_xscale[m0];
        float f1b = sw * g_xscale[m0 + 8];
        float f2a = f1a * (1.0f / 254.0f);
        float f2b = f1b * (1.0f / 254.0f);
#pragma unroll
        for (int nf = 0; nf < 4; nf++) {
            int n = n_base + wn * 32 + nf * 8 + 2 * (lane & 3);
            float2 bv = __ldg(reinterpret_cast<const float2*>(bias + n));
            float2 o0, o1;
            o0.x = (float)acc1[mf][nf][0] * f1a + (float)acc2[mf][nf][0] * f2a + bv.x;
            o0.y = (float)acc1[mf][nf][1] * f1a + (float)acc2[mf][nf][1] * f2a + bv.y;
            o1.x = (float)acc1[mf][nf][2] * f1b + (float)acc2[mf][nf][2] * f2b + bv.x;
            o1.y = (float)acc1[mf][nf][3] * f1b + (float)acc2[mf][nf][3] * f2b + bv.y;
            *reinterpret_cast<float2*>(out + (size_t)m0 * N_DIM + n) = o0;
            *reinterpret_cast<float2*>(out + (size_t)(m0 + 8) * N_DIM + n) = o1;
        }
    }
}

// ============================================================================
// Host launcher — inputs identified by element count (order-robust)
// ============================================================================
extern "C" void kernel_launch(void* const* d_in, const int* in_sizes, int n_in,
                              void* d_out, int out_size) {
    const float* x     = nullptr;
    const int*   w32   = nullptr;    // int8 weights widened to int32 by harness
    const float* scale = nullptr;
    const float* bias  = nullptr;
    for (int i = 0; i < n_in; i++) {
        switch (in_sizes[i]) {
            case M_ROWS * K_DIM: x     = (const float*)d_in[i]; break;  // 524288
            case N_DIM * K_DIM:  w32   = (const int*)d_in[i];   break;  // 45088768
            case 1:              scale = (const float*)d_in[i]; break;
            case N_DIM:          bias  = (const float*)d_in[i]; break;  // 11008
        }
    }
    float* out = (float*)d_out;

    cudaFuncSetAttribute(gemm_i8_kernel,
                         cudaFuncAttributeMaxDynamicSharedMemorySize, SMEM_TOTAL);

    quant_x_kernel<<<M_ROWS, 128>>>(x);
    gemm_i8_kernel<<<N_BLOCKS, 512, SMEM_TOTAL>>>(w32, scale, bias, out);
}

// round 5
// speedup vs baseline: 1.5879x; 1.5879x over previous
#include <cuda_runtime.h>
#include <cstdint>

// ============================================================================
// y[128, 11008] = x[128,4096] @ W[11008,4096]^T * scale + bias
// w_q arrives as int32 (harness widens int8 -> int32). Packed to s8 in-flight.
// Dual-level int8 quantization of x:  x ~ s_m*(q1 + q2/254)
// GEMM via mma.sync.m16n8k32.s8, fp32 epilogue.
// Round 5: single-wave grid. N_TILE=80 -> 138 CTAs (<=148 SMs, one wave).
// 640 threads/CTA, 4(M)x5(N) warps, warp tile 32x16.
// ============================================================================

#define M_ROWS 128
#define K_DIM  4096
#define N_DIM  11008
#define N_TILE 80
#define N_BLOCKS ((N_DIM + N_TILE - 1) / N_TILE)   // 138
#define K_STAGE 128
#define NSTAGES 4
#define NUM_STEPS (K_DIM / K_STAGE)        // 32
#define NTHREADS 640

#define SMEM_ROW 144                       // 128 + 16 pad (conflict-free LDS)
#define A_TILE_BYTES (M_ROWS * SMEM_ROW)   // 18432
#define B_TILE_BYTES (N_TILE * SMEM_ROW)   // 11520
#define STAGE_BYTES  (2 * A_TILE_BYTES + B_TILE_BYTES)   // 48384
#define SMEM_TOTAL   (NSTAGES * STAGE_BYTES)             // 193536

#define B_OFF  (2 * A_TILE_BYTES)

// ---- scratch (no cudaMalloc allowed) ----
__device__ __align__(1024) int8_t g_q1[M_ROWS * K_DIM];
__device__ __align__(1024) int8_t g_q2[M_ROWS * K_DIM];
__device__ float g_xscale[M_ROWS];

// ============================================================================
// helpers
// ============================================================================
__device__ __forceinline__ uint32_t smem_u32(const void* p) {
    uint32_t a;
    asm("{ .reg .u64 t; cvta.to.shared.u64 t, %1; cvt.u32.u64 %0, t; }"
        : "=r"(a) : "l"(p));
    return a;
}
__device__ __forceinline__ void cp16(uint32_t dst, const void* src) {
    asm volatile("cp.async.cg.shared.global [%0], [%1], 16;"
                 :: "r"(dst), "l"(src) : "memory");
}
__device__ __forceinline__ void cp_commit() {
    asm volatile("cp.async.commit_group;" ::: "memory");
}
template <int N>
__device__ __forceinline__ void cp_wait() {
    asm volatile("cp.async.wait_group %0;" :: "n"(N) : "memory");
}
__device__ __forceinline__ void mma_s8(int* d, const uint32_t* a, const uint32_t* b) {
    asm volatile(
        "mma.sync.aligned.m16n8k32.row.col.s32.s8.s8.s32 "
        "{%0,%1,%2,%3}, {%4,%5,%6,%7}, {%8,%9}, {%0,%1,%2,%3};"
        : "+r"(d[0]), "+r"(d[1]), "+r"(d[2]), "+r"(d[3])
        : "r"(a[0]), "r"(a[1]), "r"(a[2]), "r"(a[3]), "r"(b[0]), "r"(b[1]));
}
__device__ __forceinline__ uint32_t pack4(int4 v) {
    uint32_t lo = __byte_perm((uint32_t)v.x, (uint32_t)v.y, 0x0040);
    uint32_t hi = __byte_perm((uint32_t)v.z, (uint32_t)v.w, 0x0040);
    return __byte_perm(lo, hi, 0x5410);
}

// ============================================================================
// Kernel 1: quantize x rows -> (q1, q2) int8 + per-row scale
// ============================================================================
__global__ __launch_bounds__(128) void quant_x_kernel(const float* __restrict__ x) {
    int m = blockIdx.x;
    int tid = threadIdx.x;
    const float4* xr = reinterpret_cast<const float4*>(x + (size_t)m * K_DIM);

    float4 v[8];
    float vmax = 0.f;
#pragma unroll
    for (int i = 0; i < 8; i++) {
        v[i] = xr[tid + i * 128];
        vmax = fmaxf(vmax, fmaxf(fmaxf(fabsf(v[i].x), fabsf(v[i].y)),
                                 fmaxf(fabsf(v[i].z), fabsf(v[i].w))));
    }
#pragma unroll
    for (int o = 16; o > 0; o >>= 1)
        vmax = fmaxf(vmax, __shfl_xor_sync(0xffffffffu, vmax, o));

    __shared__ float smax[4];
    if ((tid & 31) == 0) smax[tid >> 5] = vmax;
    __syncthreads();
    vmax = fmaxf(fmaxf(smax[0], smax[1]), fmaxf(smax[2], smax[3]));

    float inv = (vmax > 0.f) ? (127.0f / vmax) : 0.0f;
    float sm  = (vmax > 0.f) ? (vmax / 127.0f) : 1.0f;
    if (tid == 0) g_xscale[m] = sm;

    char4* o1 = reinterpret_cast<char4*>(g_q1 + (size_t)m * K_DIM);
    char4* o2 = reinterpret_cast<char4*>(g_q2 + (size_t)m * K_DIM);

#pragma unroll
    for (int i = 0; i < 8; i++) {
        float t[4] = {v[i].x * inv, v[i].y * inv, v[i].z * inv, v[i].w * inv};
        char q1c[4], q2c[4];
#pragma unroll
        for (int j = 0; j < 4; j++) {
            float q1 = rintf(t[j]);
            float q2 = rintf((t[j] - q1) * 254.0f);
            q1c[j] = (char)(int)q1;
            q2c[j] = (char)(int)q2;
        }
        o1[tid + i * 128] = make_char4(q1c[0], q1c[1], q1c[2], q1c[3]);
        o2[tid + i * 128] = make_char4(q2c[0], q2c[1], q2c[2], q2c[3]);
    }
}

// ============================================================================
// Kernel 2: GEMM. 138 CTAs x 640 threads. CTA tile 128(M) x 80(N).
// 4x5 warp grid, warp tile 32x16. 4-stage ring:
//   A1/A2 (int8 g_q1/g_q2): cp.async (threads 0..511), 2 stages ahead
//   B (int32 W): LDG.128 2 ahead -> pack s8 -> STS after compute
// ============================================================================
__global__ __launch_bounds__(NTHREADS, 1) void gemm_i8_kernel(
    const int* __restrict__ w32,
    const float* __restrict__ scale,
    const float* __restrict__ bias,
    float* __restrict__ out)
{
    extern __shared__ char smem[];
    const uint32_t sb = smem_u32(smem);
    const int tid = threadIdx.x;
    const int wid = tid >> 5;
    const int lane = tid & 31;
    const int wm = wid & 3;        // warp M index (0..3)
    const int wn = wid >> 2;       // warp N index (0..4)
    const int n_base = blockIdx.x * N_TILE;

    // ---- A-side cp.async (threads 0..511, 4 x 16B per stage) ---------------
    uint32_t cpA_dst[4];
    const int8_t* cpA_src[4];
    if (tid < 512) {
#pragma unroll
        for (int i = 0; i < 4; i++) {
            int c = tid + i * 512;           // [0, 2048)
            int which = c >> 10;             // 0:A1 1:A2
            int r = (c & 1023) >> 3;         // m row 0..127
            int col = (c & 7) * 16;          // k byte 0..112
            cpA_dst[i] = sb + which * A_TILE_BYTES + r * SMEM_ROW + col;
            cpA_src[i] = (which ? g_q2 : g_q1) + (size_t)r * K_DIM + col;
        }
    }
    auto issueA = [&](int s) {
        if (tid < 512) {
            uint32_t buf_off = (uint32_t)((s & (NSTAGES - 1)) * STAGE_BYTES);
            int k0 = s * K_STAGE;
#pragma unroll
            for (int i = 0; i < 4; i++)
                cp16(cpA_dst[i] + buf_off, cpA_src[i] + k0);
            cp_commit();
        }
    };

    // ---- B-side: 4 x LDG.128 per thread per stage --------------------------
    const int wr = tid >> 5;            // base n-row 0..19 (rows wr + 20j)
    const int c4 = lane * 4;            // int32 idx within row (= packed byte col)
    const int* wsrc[4];
#pragma unroll
    for (int j = 0; j < 4; j++) {
        int rg = n_base + wr + 20 * j;
        if (rg > N_DIM - 1) rg = N_DIM - 1;   // clamp (ragged last tile)
        wsrc[j] = w32 + (size_t)rg * K_DIM + c4;
    }

    int4 breg[4];
    auto ldgB = [&](int s) {
        const int k0 = s * K_STAGE;
#pragma unroll
        for (int j = 0; j < 4; j++)
            breg[j] = *reinterpret_cast<const int4*>(wsrc[j] + k0);
    };
    auto stsB = [&](int s) {
        char* dst = smem + (s & (NSTAGES - 1)) * STAGE_BYTES + B_OFF
                         + wr * SMEM_ROW + c4;
#pragma unroll
        for (int j = 0; j < 4; j++)
            *reinterpret_cast<uint32_t*>(dst + j * 20 * SMEM_ROW) = pack4(breg[j]);
    };

    // ---- prologue: stages 0,1 ----------------------------------------------
    issueA(0);
    issueA(1);
    ldgB(0); stsB(0);
    ldgB(1); stsB(1);

    // ---- per-lane fragment base pointers (PTX m16n8k32.s8 spec) ------------
    const int g  = lane >> 2;
    const int t4 = (lane & 3) * 4;
    const char* A1p = smem + (wm * 32 + g) * SMEM_ROW + t4;
    const char* Bp  = smem + B_OFF + (wn * 16 + g) * SMEM_ROW + t4;

    int acc1[2][2][4] = {};
    int acc2[2][2][4] = {};

    // ---- main loop ---------------------------------------------------------
    for (int s = 0; s < NUM_STEPS; s++) {
        cp_wait<1>();          // A stage s landed (participating threads)
        __syncthreads();       // publish everyone's A + B(stage s)

        if (s + 2 < NUM_STEPS) { ldgB(s + 2); issueA(s + 2); }
        else if (tid < 512)    { cp_commit(); }   // keep wait accounting sound

        const int buf = (s & (NSTAGES - 1)) * STAGE_BYTES;
#pragma unroll
        for (int ks = 0; ks < 4; ks++) {
            const int off = buf + ks * 32;
            uint32_t a1f[2][4], a2f[2][4], bfr[2][2];
#pragma unroll
            for (int mf = 0; mf < 2; mf++) {
                const char* r1 = A1p + off + mf * (16 * SMEM_ROW);
                a1f[mf][0] = *(const uint32_t*)(r1);
                a1f[mf][1] = *(const uint32_t*)(r1 + 8 * SMEM_ROW);
                a1f[mf][2] = *(const uint32_t*)(r1 + 16);
                a1f[mf][3] = *(const uint32_t*)(r1 + 8 * SMEM_ROW + 16);
                const char* r2 = r1 + A_TILE_BYTES;
                a2f[mf][0] = *(const uint32_t*)(r2);
                a2f[mf][1] = *(const uint32_t*)(r2 + 8 * SMEM_ROW);
                a2f[mf][2] = *(const uint32_t*)(r2 + 16);
                a2f[mf][3] = *(const uint32_t*)(r2 + 8 * SMEM_ROW + 16);
            }
#pragma unroll
            for (int nf = 0; nf < 2; nf++) {
                const char* rb = Bp + off + nf * (8 * SMEM_ROW);
                bfr[nf][0] = *(const uint32_t*)(rb);
                bfr[nf][1] = *(const uint32_t*)(rb + 16);
            }
#pragma unroll
            for (int mf = 0; mf < 2; mf++) {
#pragma unroll
                for (int nf = 0; nf < 2; nf++) {
                    mma_s8(acc1[mf][nf], a1f[mf], bfr[nf]);
                    mma_s8(acc2[mf][nf], a2f[mf], bfr[nf]);
                }
            }
        }

        if (s + 2 < NUM_STEPS) stsB(s + 2);   // ring distance 2 (!= s mod 4)
    }

    // ---- epilogue ----------------------------------------------------------
    const float sw = __ldg(scale);
    const int mrow0 = wm * 32 + g;
#pragma unroll
    for (int mf = 0; mf < 2; mf++) {
        int m0 = mrow0 + mf * 16;
        float f1a = sw * g_xscale[m0];
        float f1b = sw * g_xscale[m0 + 8];
        float f2a = f1a * (1.0f / 254.0f);
        float f2b = f1b * (1.0f / 254.0f);
#pragma unroll
        for (int nf = 0; nf < 2; nf++) {
            int n = n_base + wn * 16 + nf * 8 + 2 * (lane & 3);
            if (n < N_DIM) {
                float2 bv = __ldg(reinterpret_cast<const float2*>(bias + n));
                float2 o0, o1;
                o0.x = (float)acc1[mf][nf][0] * f1a + (float)acc2[mf][nf][0] * f2a + bv.x;
                o0.y = (float)acc1[mf][nf][1] * f1a + (float)acc2[mf][nf][1] * f2a + bv.y;
                o1.x = (float)acc1[mf][nf][2] * f1b + (float)acc2[mf][nf][2] * f2b + bv.x;
                o1.y = (float)acc1[mf][nf][3] * f1b + (float)acc2[mf][nf][3] * f2b + bv.y;
                *reinterpret_cast<float2*>(out + (size_t)m0 * N_DIM + n) = o0;
                *reinterpret_cast<float2*>(out + (size_t)(m0 + 8) * N_DIM + n) = o1;
            }
        }
    }
}

// ============================================================================
// Host launcher — inputs identified by element count (order-robust)
// ============================================================================
extern "C" void kernel_launch(void* const* d_in, const int* in_sizes, int n_in,
                              void* d_out, int out_size) {
    const float* x     = nullptr;
    const int*   w32   = nullptr;    // int8 weights widened to int32 by harness
    const float* scale = nullptr;
    const float* bias  = nullptr;
    for (int i = 0; i < n_in; i++) {
        switch (in_sizes[i]) {
            case M_ROWS * K_DIM: x     = (const float*)d_in[i]; break;  // 524288
            case N_DIM * K_DIM:  w32   = (const int*)d_in[i];   break;  // 45088768
            case 1:              scale = (const float*)d_in[i]; break;
            case N_DIM:          bias  = (const float*)d_in[i]; break;  // 11008
        }
    }
    float* out = (float*)d_out;

    cudaFuncSetAttribute(gemm_i8_kernel,
                         cudaFuncAttributeMaxDynamicSharedMemorySize, SMEM_TOTAL);

    quant_x_kernel<<<M_ROWS, 128>>>(x);
    gemm_i8_kernel<<<N_BLOCKS, NTHREADS, SMEM_TOTAL>>>(w32, scale, bias, out);
}